// round 14
// baseline (speedup 1.0000x reference)
#include <cuda_runtime.h>
#include <cuda_fp16.h>
#include <cstdint>

#define B_SAMPLES 32768
#define N_CLASSES 10
#define UNIT 16
#define D_IN 160
#define D_IN_PAD 192
#define H1_DIM 512
#define H2_DIM 1024
#define O_DIM 3072

// ---------------- scratch ----------------
// g_w1 sized for K padding: rows 160..191 stay zero (device globals zero-init)
__device__ __align__(128) __half g_h1[(size_t)B_SAMPLES * H1_DIM];
__device__ __align__(128) __half g_h2[(size_t)B_SAMPLES * H2_DIM];
__device__ __align__(128) __half g_w1[(size_t)D_IN_PAD * H1_DIM];
__device__ __align__(128) __half g_w2[(size_t)H1_DIM * H2_DIM];
__device__ __align__(128) __half g_w3[(size_t)H2_DIM * O_DIM];

#define W1_N2 (D_IN * H1_DIM / 2)
#define W2_N2 (H1_DIM * H2_DIM / 2)
#define W3_N2 (H2_DIM * O_DIM / 2)

// ---------------- merged fp32 -> fp16 ----------------
__global__ void f2h_all(const float2* __restrict__ w1,
                        const float2* __restrict__ w2,
                        const float2* __restrict__ w3,
                        __half2* __restrict__ o1,
                        __half2* __restrict__ o2,
                        __half2* __restrict__ o3) {
    const int total = W1_N2 + W2_N2 + W3_N2;
    int i = blockIdx.x * blockDim.x + threadIdx.x;
    int stride = gridDim.x * blockDim.x;
    for (; i < total; i += stride) {
        float2 v;
        __half2* dst;
        if (i < W1_N2) {
            v = w1[i];
            dst = o1 + i;
        } else if (i < W1_N2 + W2_N2) {
            v = w2[i - W1_N2];
            dst = o2 + (i - W1_N2);
        } else {
            v = w3[i - W1_N2 - W2_N2];
            dst = o3 + (i - W1_N2 - W2_N2);
        }
        *dst = __floats2half2_rn(v.x, v.y);
    }
}

// ---------------- mma helpers ----------------
__device__ __forceinline__ void ldm_x4(uint32_t& r0, uint32_t& r1,
                                       uint32_t& r2, uint32_t& r3,
                                       uint32_t addr) {
    asm volatile("ldmatrix.sync.aligned.m8n8.x4.shared.b16 {%0,%1,%2,%3}, [%4];\n"
                 : "=r"(r0), "=r"(r1), "=r"(r2), "=r"(r3)
                 : "r"(addr));
}

__device__ __forceinline__ void ldm_x4_t(uint32_t& r0, uint32_t& r1,
                                         uint32_t& r2, uint32_t& r3,
                                         uint32_t addr) {
    asm volatile("ldmatrix.sync.aligned.m8n8.x4.trans.shared.b16 {%0,%1,%2,%3}, [%4];\n"
                 : "=r"(r0), "=r"(r1), "=r"(r2), "=r"(r3)
                 : "r"(addr));
}

__device__ __forceinline__ void mma_f16(uint32_t* c, const uint32_t* a,
                                        const uint32_t* b) {
    asm volatile(
        "mma.sync.aligned.m16n8k16.row.col.f16.f16.f16.f16 "
        "{%0,%1}, {%2,%3,%4,%5}, {%6,%7}, {%0,%1};\n"
        : "+r"(c[0]), "+r"(c[1])
        : "r"(a[0]), "r"(a[1]), "r"(a[2]), "r"(a[3]), "r"(b[0]), "r"(b[1]));
}

// ---------------- geometry (GEMM2/3, unchanged from R13) ----------------
#define BK 64
#define A_LDS 72     // 64 + 8 (halves)
#define B_LDS 136    // 128 + 8 (halves)
#define STAGES 2
#define A_STG (128 * A_LDS)
#define B_STG (BK * B_LDS)
#define SMEM_BYTES (STAGES * (A_STG + B_STG) * 2)   // 71680 B

__device__ __forceinline__ void ld_stage(uint32_t sA, uint32_t sB,
                                         const __half* __restrict__ A,
                                         const __half* __restrict__ Bm,
                                         int bm, int bn, int K, int N, int t,
                                         int tid) {
    const __half* Ag = A + (size_t)bm * K + t * BK;
    const __half* Bg = Bm + (size_t)t * BK * N + bn;
#pragma unroll
    for (int i = 0; i < 4; i++) {
        int q = tid + i * 256;
        int ar = q >> 3, ac = (q & 7) * 8;
        asm volatile("cp.async.cg.shared.global [%0], [%1], 16;" ::
                     "r"(sA + (uint32_t)(ar * A_LDS + ac) * 2u),
                     "l"(Ag + (size_t)ar * K + ac));
        int br = q >> 4, bc = (q & 15) * 8;
        asm volatile("cp.async.cg.shared.global [%0], [%1], 16;" ::
                     "r"(sB + (uint32_t)(br * B_LDS + bc) * 2u),
                     "l"(Bg + (size_t)br * N + bc));
    }
    asm volatile("cp.async.commit_group;" ::: "memory");
}

// ================= GEMM2/3: tile 128x128, warp 32x64, 3 CTAs/SM (R13) =======
template <int ACT>
__global__ __launch_bounds__(256, 3) void gemm_kernel(
    const __half* __restrict__ A,
    const __half* __restrict__ Bm,
    const float* __restrict__ bias,
    void* __restrict__ Cout,
    int N, int K) {
    extern __shared__ __half smem[];

    const int tid = threadIdx.x;
    const int warp = tid >> 5;
    const int lane = tid & 31;
    const int warpM = warp >> 1;
    const int warpN = warp & 1;
    const int bm = blockIdx.y * 128;
    const int bn = blockIdx.x * 128;

    const uint32_t sBase = (uint32_t)__cvta_generic_to_shared(smem);
    const uint32_t aBase = sBase;
    const uint32_t bBase = sBase + (uint32_t)STAGES * A_STG * 2u;

    const uint32_t aOffBase =
        (uint32_t)((warpM * 32 + (lane & 15)) * A_LDS + ((lane >> 4) << 3)) * 2u;
    const uint32_t bOffBase =
        (uint32_t)((lane & 15) * B_LDS + warpN * 64 + ((lane >> 4) << 3)) * 2u;

    uint32_t acc[2][8][2];
#pragma unroll
    for (int mt = 0; mt < 2; mt++)
#pragma unroll
        for (int n8 = 0; n8 < 8; n8++) {
            acc[mt][n8][0] = 0u;
            acc[mt][n8][1] = 0u;
        }

    const int T = K / BK;

    ld_stage(aBase, bBase, A, Bm, bm, bn, K, N, 0, tid);

    for (int t = 0; t < T; t++) {
        if (t + 1 < T) {
            int sl = (t + 1) & 1;
            ld_stage(aBase + (uint32_t)sl * A_STG * 2u,
                     bBase + (uint32_t)sl * B_STG * 2u,
                     A, Bm, bm, bn, K, N, t + 1, tid);
        } else {
            asm volatile("cp.async.commit_group;" ::: "memory");
        }
        asm volatile("cp.async.wait_group 1;" ::: "memory");
        __syncthreads();

        const int s = t & 1;
        const uint32_t sA = aBase + (uint32_t)s * A_STG * 2u + aOffBase;
        const uint32_t sB = bBase + (uint32_t)s * B_STG * 2u + bOffBase;

#pragma unroll
        for (int kk = 0; kk < 4; kk++) {
            uint32_t a[2][4];
#pragma unroll
            for (int mt = 0; mt < 2; mt++)
                ldm_x4(a[mt][0], a[mt][1], a[mt][2], a[mt][3],
                       sA + (uint32_t)(mt * 16 * A_LDS + kk * 16) * 2u);
            uint32_t b[8][2];
#pragma unroll
            for (int nt = 0; nt < 4; nt++) {
                uint32_t r0, r1, r2, r3;
                ldm_x4_t(r0, r1, r2, r3,
                         sB + (uint32_t)(kk * 16 * B_LDS + nt * 16) * 2u);
                b[2 * nt][0] = r0; b[2 * nt][1] = r1;
                b[2 * nt + 1][0] = r2; b[2 * nt + 1][1] = r3;
            }
#pragma unroll
            for (int mt = 0; mt < 2; mt++)
#pragma unroll
                for (int n8 = 0; n8 < 8; n8++)
                    mma_f16(acc[mt][n8], a[mt], b[n8]);
        }
        __syncthreads();
    }

    const int lr = lane >> 2;
    const int lc = (lane & 3) * 2;
#pragma unroll
    for (int mt = 0; mt < 2; mt++) {
#pragma unroll
        for (int n8 = 0; n8 < 8; n8++) {
            int row0 = bm + warpM * 32 + mt * 16 + lr;
            int col = bn + warpN * 64 + n8 * 8 + lc;
            float bz0 = __ldg(bias + col);
            float bz1 = __ldg(bias + col + 1);
            float2 p0 = __half22float2(*(__half2*)&acc[mt][n8][0]);
            float2 p1 = __half22float2(*(__half2*)&acc[mt][n8][1]);
            float v00 = p0.x + bz0;
            float v01 = p0.y + bz1;
            float v10 = p1.x + bz0;
            float v11 = p1.y + bz1;
            if (ACT == 0) {
                v00 = fmaxf(v00, 0.f); v01 = fmaxf(v01, 0.f);
                v10 = fmaxf(v10, 0.f); v11 = fmaxf(v11, 0.f);
                __half* C = (__half*)Cout;
                *(__half2*)&C[(size_t)row0 * N + col] = __floats2half2_rn(v00, v01);
                *(__half2*)&C[(size_t)(row0 + 8) * N + col] = __floats2half2_rn(v10, v11);
            } else {
                v00 = 1.f / (1.f + __expf(-v00));
                v01 = 1.f / (1.f + __expf(-v01));
                v10 = 1.f / (1.f + __expf(-v10));
                v11 = 1.f / (1.f + __expf(-v11));
                float* C = (float*)Cout;
                *(float2*)&C[(size_t)row0 * N + col] = make_float2(v00, v01);
                *(float2*)&C[(size_t)(row0 + 8) * N + col] = make_float2(v10, v11);
            }
        }
    }
}

// ================= GEMM1 fused with capsule mask =================
// A tile built in smem from x (argmax + scatter), B staged via cp.async.
// K=192 (3 k-tiles), tile 128x128, warp 32x64.
#define A1_LDS 200                     // 192 + 8 halves; (200/8)=25 odd: LDSM-safe
#define A1_BYTES (128 * A1_LDS * 2)    // 51200
#define G1_SMEM (A1_BYTES + STAGES * B_STG * 2)   // 51200 + 34816 = 86016

__global__ __launch_bounds__(256, 2) void gemm1_fused(
    const float* __restrict__ x,
    const __half* __restrict__ Bm,
    const float* __restrict__ bias,
    __half* __restrict__ Cout) {
    extern __shared__ __half smem[];
    const int N = H1_DIM;

    const int tid = threadIdx.x;
    const int warp = tid >> 5;
    const int lane = tid & 31;
    const int warpM = warp >> 1;
    const int warpN = warp & 1;
    const int bm = blockIdx.y * 128;
    const int bn = blockIdx.x * 128;

    const uint32_t sBase = (uint32_t)__cvta_generic_to_shared(smem);
    const uint32_t aBase = sBase;                      // static A tile
    const uint32_t bBase = sBase + (uint32_t)A1_BYTES; // B stages

    // start B stage 0 load immediately (overlaps with mask phase)
    {
        const __half* Bg = Bm + bn;
#pragma unroll
        for (int i = 0; i < 4; i++) {
            int q = tid + i * 256;
            int br = q >> 4, bc = (q & 15) * 8;
            asm volatile("cp.async.cg.shared.global [%0], [%1], 16;" ::
                         "r"(bBase + (uint32_t)(br * B_LDS + bc) * 2u),
                         "l"(Bg + (size_t)br * N + bc));
        }
        asm volatile("cp.async.commit_group;" ::: "memory");
    }

    // zero-fill A tile (128 * 200 halves = 3200 uint4)
    for (int q = tid; q < 3200; q += 256)
        *reinterpret_cast<uint4*>(smem + q * 8) = make_uint4(0u, 0u, 0u, 0u);
    __syncthreads();

    // capsule argmax: 2 threads per row, 5 capsules each
    {
        const int row = tid >> 1;
        const int h = tid & 1;
        const float* xr = x + (size_t)(bm + row) * D_IN + h * 80;
        float best = -1.f;
        int bc_ = 0;
#pragma unroll
        for (int c = 0; c < 5; c++) {
            float s = 0.f;
#pragma unroll
            for (int j = 0; j < 4; j++) {
                float4 v = __ldg((const float4*)(xr + c * UNIT + j * 4));
                s += v.x * v.x + v.y * v.y + v.z * v.z + v.w * v.w;
            }
            if (s > best) { best = s; bc_ = c; }
        }
        float ob = __shfl_xor_sync(0xFFFFFFFFu, best, 1);
        // first-max tie rule: h=0 wins ties (its capsules have lower indices)
        bool iwin = (h == 0) ? (best >= ob) : (best > ob);
        if (iwin) {
            const float* cp = xr + bc_ * UNIT;
            uint4 pk[2];
#pragma unroll
            for (int half_ = 0; half_ < 2; half_++) {
                float4 f0 = __ldg((const float4*)(cp + half_ * 8));
                float4 f1 = __ldg((const float4*)(cp + half_ * 8 + 4));
                __half2 h0 = __floats2half2_rn(f0.x, f0.y);
                __half2 h1 = __floats2half2_rn(f0.z, f0.w);
                __half2 h2 = __floats2half2_rn(f1.x, f1.y);
                __half2 h3 = __floats2half2_rn(f1.z, f1.w);
                pk[half_].x = *(uint32_t*)&h0;
                pk[half_].y = *(uint32_t*)&h1;
                pk[half_].z = *(uint32_t*)&h2;
                pk[half_].w = *(uint32_t*)&h3;
            }
            int gbi = h * 5 + bc_;
            uint4* dst = reinterpret_cast<uint4*>(smem + row * A1_LDS + gbi * UNIT);
            dst[0] = pk[0];
            dst[1] = pk[1];
        }
    }
    __syncthreads();

    const uint32_t aOffBase =
        (uint32_t)((warpM * 32 + (lane & 15)) * A1_LDS + ((lane >> 4) << 3)) * 2u;
    const uint32_t bOffBase =
        (uint32_t)((lane & 15) * B_LDS + warpN * 64 + ((lane >> 4) << 3)) * 2u;

    uint32_t acc[2][8][2];
#pragma unroll
    for (int mt = 0; mt < 2; mt++)
#pragma unroll
        for (int n8 = 0; n8 < 8; n8++) {
            acc[mt][n8][0] = 0u;
            acc[mt][n8][1] = 0u;
        }

    const int T = D_IN_PAD / BK;  // 3
#pragma unroll
    for (int t = 0; t < T; t++) {
        if (t + 1 < T) {
            int sl = (t + 1) & 1;
            const __half* Bg = Bm + (size_t)(t + 1) * BK * N + bn;
#pragma unroll
            for (int i = 0; i < 4; i++) {
                int q = tid + i * 256;
                int br = q >> 4, bc = (q & 15) * 8;
                asm volatile("cp.async.cg.shared.global [%0], [%1], 16;" ::
                             "r"(bBase + (uint32_t)(sl * B_STG + br * B_LDS + bc) * 2u),
                             "l"(Bg + (size_t)br * N + bc));
            }
            asm volatile("cp.async.commit_group;" ::: "memory");
        } else {
            asm volatile("cp.async.commit_group;" ::: "memory");
        }
        asm volatile("cp.async.wait_group 1;" ::: "memory");
        __syncthreads();

        const int s = t & 1;
        const uint32_t sA = aBase + aOffBase + (uint32_t)(t * BK) * 2u;
        const uint32_t sB = bBase + (uint32_t)s * B_STG * 2u + bOffBase;

#pragma unroll
        for (int kk = 0; kk < 4; kk++) {
            uint32_t a[2][4];
#pragma unroll
            for (int mt = 0; mt < 2; mt++)
                ldm_x4(a[mt][0], a[mt][1], a[mt][2], a[mt][3],
                       sA + (uint32_t)(mt * 16 * A1_LDS + kk * 16) * 2u);
            uint32_t b[8][2];
#pragma unroll
            for (int nt = 0; nt < 4; nt++) {
                uint32_t r0, r1, r2, r3;
                ldm_x4_t(r0, r1, r2, r3,
                         sB + (uint32_t)(kk * 16 * B_LDS + nt * 16) * 2u);
                b[2 * nt][0] = r0; b[2 * nt][1] = r1;
                b[2 * nt + 1][0] = r2; b[2 * nt + 1][1] = r3;
            }
#pragma unroll
            for (int mt = 0; mt < 2; mt++)
#pragma unroll
                for (int n8 = 0; n8 < 8; n8++)
                    mma_f16(acc[mt][n8], a[mt], b[n8]);
        }
        __syncthreads();
    }

    // epilogue: relu -> half
    const int lr = lane >> 2;
    const int lc = (lane & 3) * 2;
#pragma unroll
    for (int mt = 0; mt < 2; mt++) {
#pragma unroll
        for (int n8 = 0; n8 < 8; n8++) {
            int row0 = bm + warpM * 32 + mt * 16 + lr;
            int col = bn + warpN * 64 + n8 * 8 + lc;
            float bz0 = __ldg(bias + col);
            float bz1 = __ldg(bias + col + 1);
            float2 p0 = __half22float2(*(__half2*)&acc[mt][n8][0]);
            float2 p1 = __half22float2(*(__half2*)&acc[mt][n8][1]);
            float v00 = fmaxf(p0.x + bz0, 0.f);
            float v01 = fmaxf(p0.y + bz1, 0.f);
            float v10 = fmaxf(p1.x + bz0, 0.f);
            float v11 = fmaxf(p1.y + bz1, 0.f);
            *(__half2*)&Cout[(size_t)row0 * N + col] = __floats2half2_rn(v00, v01);
            *(__half2*)&Cout[(size_t)(row0 + 8) * N + col] = __floats2half2_rn(v10, v11);
        }
    }
}

// ---------------- launch ----------------
extern "C" void kernel_launch(void* const* d_in, const int* in_sizes, int n_in,
                              void* d_out, int out_size) {
    const float* x  = (const float*)d_in[0];
    const float* W1 = (const float*)d_in[2];
    const float* b1 = (const float*)d_in[3];
    const float* W2 = (const float*)d_in[4];
    const float* b2 = (const float*)d_in[5];
    const float* W3 = (const float*)d_in[6];
    const float* b3 = (const float*)d_in[7];

    void *ph1, *ph2, *pw1, *pw2, *pw3;
    cudaGetSymbolAddress(&ph1, g_h1);
    cudaGetSymbolAddress(&ph2, g_h2);
    cudaGetSymbolAddress(&pw1, g_w1);
    cudaGetSymbolAddress(&pw2, g_w2);
    cudaGetSymbolAddress(&pw3, g_w3);
    __half* h1  = (__half*)ph1;
    __half* h2  = (__half*)ph2;
    __half* w1h = (__half*)pw1;
    __half* w2h = (__half*)pw2;
    __half* w3h = (__half*)pw3;

    cudaFuncSetAttribute(gemm1_fused,
                         cudaFuncAttributeMaxDynamicSharedMemorySize, G1_SMEM);
    cudaFuncSetAttribute(gemm_kernel<0>,
                         cudaFuncAttributeMaxDynamicSharedMemorySize, SMEM_BYTES);
    cudaFuncSetAttribute(gemm_kernel<1>,
                         cudaFuncAttributeMaxDynamicSharedMemorySize, SMEM_BYTES);

    f2h_all<<<592, 256>>>((const float2*)W1, (const float2*)W2,
                          (const float2*)W3, (__half2*)w1h,
                          (__half2*)w2h, (__half2*)w3h);

    gemm1_fused<<<dim3(H1_DIM / 128, B_SAMPLES / 128), 256, G1_SMEM>>>(
        x, w1h, b1, h1);
    gemm_kernel<0><<<dim3(H2_DIM / 128, B_SAMPLES / 128), 256, SMEM_BYTES>>>(
        h1, w2h, b2, h2, H2_DIM, H1_DIM);
    gemm_kernel<1><<<dim3(O_DIM / 128, B_SAMPLES / 128), 256, SMEM_BYTES>>>(
        h2, w3h, b3, d_out, O_DIM, H2_DIM);
}